// round 1
// baseline (speedup 1.0000x reference)
#include <cuda_runtime.h>
#include <cuda_bf16.h>

// ---------------------------------------------------------------------------
// MLP_TI_Gram: y = MLP(mean-of-shifted-diagonal of per-batch Gram matrix)
// Key identity: diag-mean == circular autocorrelation of x over sequence dim,
// summed over the 3 channels, divided by N. Also c[r] == c[N-r] (symmetry).
// B = 128, N = 1024, H = 128.
// ---------------------------------------------------------------------------

#define BATCH 128
#define NSEQ  1024
#define HID   128

__device__ float g_c[BATCH * NSEQ];    // correlation output (scratch)
__device__ float g_h1[BATCH * HID];    // layer-1 activations (scratch)

// ---- f32x2 packed helpers (Blackwell FFMA2 path, PTX-only) ----------------
__device__ __forceinline__ unsigned long long pk2(float lo, float hi) {
    unsigned long long r;
    asm("mov.b64 %0, {%1,%2};" : "=l"(r) : "f"(lo), "f"(hi));
    return r;
}
__device__ __forceinline__ void upk2(unsigned long long v, float& lo, float& hi) {
    asm("mov.b64 {%0,%1}, %2;" : "=f"(lo), "=f"(hi) : "l"(v));
}
__device__ __forceinline__ unsigned long long fma2(unsigned long long a,
                                                   unsigned long long b,
                                                   unsigned long long c) {
    unsigned long long d;
    asm("fma.rn.f32x2 %0, %1, %2, %3;" : "=l"(d) : "l"(a), "l"(b), "l"(c));
    return d;
}

// Bank-conflict padding: logical index i -> physical i + (i>>3).
// All hot bases are multiples of 8, so per-m-step bases are affine in u.
__device__ __forceinline__ int pbase(int i) { return i + (i >> 3); }

// ---------------------------------------------------------------------------
// Kernel 1: circular autocorrelation with symmetry.
// 128 blocks (one per batch), 256 threads.
// Thread t: shift group g = t&63 (8 consecutive shifts r0=8g .. r0+7),
//           j-split  s = t>>6 covering j in [128s,128s+128) U [128s+512,+128).
// Channels 0,1 packed per position; channel 2 packed across the two j-ranges.
// Sliding register windows: 2 LDS.64 per 24 packed FMAs per u-step.
// ---------------------------------------------------------------------------
__global__ __launch_bounds__(256, 1)
void corr_kernel(const float* __restrict__ x) {
    // xs01[i] = (x0[i%N], x1[i%N]) for i in [0,1536): covers j+512+r (<=1535)
    __shared__ unsigned long long xs01[1736];   // pbase(1535)=1726
    // xs2ab[i] = (x2[i], x2[(i+512)&1023]) for i in [0,1024)
    __shared__ unsigned long long xs2ab[1160];  // pbase(1023)=1150
    __shared__ float red[4][512];

    const int b = blockIdx.x;
    const int t = threadIdx.x;
    const float* __restrict__ xb = x + b * NSEQ * 3;

    for (int i = t; i < 1536; i += 256) {
        int j = i & (NSEQ - 1);
        xs01[pbase(i)] = pk2(xb[j * 3 + 0], xb[j * 3 + 1]);
    }
    for (int i = t; i < 1024; i += 256) {
        xs2ab[pbase(i)] = pk2(xb[i * 3 + 2], xb[((i + 512) & (NSEQ - 1)) * 3 + 2]);
    }
    __syncthreads();

    const int g  = t & 63;
    const int s  = t >> 6;
    const int r0 = g << 3;
    const int mA = s << 7;

    unsigned long long w01a[8], w01b[8], w2[8];
    unsigned long long acc01a[8], acc01b[8], acc2[8];
#pragma unroll
    for (int k = 0; k < 8; k++) { acc01a[k] = 0ull; acc01b[k] = 0ull; acc2[k] = 0ull; }

    // initial windows: w[k] = xs[mA + r0 + k]
    {
        int bA = pbase(mA + r0);
        int bB = pbase(mA + 512 + r0);
#pragma unroll
        for (int k = 0; k < 8; k++) {
            w01a[k] = xs01[bA + k];
            w01b[k] = xs01[bB + k];
            w2[k]   = xs2ab[bA + k];
        }
    }

#pragma unroll 1
    for (int m = mA; m < mA + 128; m += 8) {
        const int baseA  = pbase(m);
        const int baseB  = pbase(m + 512);
        const int rbaseA = pbase(m + r0 + 8);
        const int rbaseB = pbase(m + 512 + r0 + 8);
#pragma unroll
        for (int u = 0; u < 8; u++) {
            unsigned long long a01a = xs01[baseA + u];
            unsigned long long a01b = xs01[baseB + u];
            unsigned long long a2   = xs2ab[baseA + u];
#pragma unroll
            for (int k = 0; k < 8; k++) {
                int idx = (u + k) & 7;
                acc01a[k] = fma2(a01a, w01a[idx], acc01a[k]);
                acc01b[k] = fma2(a01b, w01b[idx], acc01b[k]);
                acc2[k]   = fma2(a2,   w2[idx],   acc2[k]);
            }
            w01a[u] = xs01[rbaseA + u];
            w01b[u] = xs01[rbaseB + u];
            w2[u]   = xs2ab[rbaseA + u];
        }
    }

#pragma unroll
    for (int k = 0; k < 8; k++) {
        float ax, ay, bx, by, cx, cy;
        upk2(acc01a[k], ax, ay);
        upk2(acc01b[k], bx, by);
        upk2(acc2[k],   cx, cy);
        red[s][r0 + k] = ax + ay + bx + by + cx + cy;
    }
    __syncthreads();

    const float inv = 1.0f / (float)NSEQ;
    for (int r = t; r < 512; r += 256) {
        float v = (red[0][r] + red[1][r] + red[2][r] + red[3][r]) * inv;
        g_c[b * NSEQ + r] = v;
        if (r > 0) g_c[b * NSEQ + (NSEQ - r)] = v;   // symmetry c[r] = c[N-r]
    }

    // r = 512 (self-mirror): c[512] = 2 * sum_{j<512} sum_d xd[j]*xd[j+512]
    if (t < 32) {
        float sum = 0.0f;
        for (int j = t; j < 512; j += 32) {
            float p0x, p0y, q0x, q0y, cx, cy;
            upk2(xs01[pbase(j)], p0x, p0y);
            upk2(xs01[pbase(j + 512)], q0x, q0y);
            upk2(xs2ab[pbase(j)], cx, cy);
            sum += p0x * q0x + p0y * q0y + cx * cy;
        }
        sum *= 2.0f;
#pragma unroll
        for (int o = 16; o > 0; o >>= 1) sum += __shfl_down_sync(0xffffffffu, sum, o);
        if (t == 0) g_c[b * NSEQ + 512] = sum * inv;
    }
}

__device__ __forceinline__ float celu1(float v) {
    return v > 0.0f ? v : expm1f(v);
}

// ---------------------------------------------------------------------------
// Kernel 2: layer 1 — h1 = celu(c @ W1 + b1).
// 64 blocks: each handles a batch pair, streams W1 once (LDG.128, L2-resident).
// 128 threads = 4 warps (j-quarters) x 32 lanes (h-quads).
// ---------------------------------------------------------------------------
__global__ __launch_bounds__(128, 1)
void mlp1_kernel(const float* __restrict__ W1, const float* __restrict__ b1) {
    __shared__ float c0s[NSEQ], c1s[NSEQ];
    __shared__ float part[4][2][HID];

    const int b0 = blockIdx.x * 2;
    const int t  = threadIdx.x;

    for (int i = t; i < NSEQ; i += 128) {
        c0s[i] = g_c[b0 * NSEQ + i];
        c1s[i] = g_c[(b0 + 1) * NSEQ + i];
    }
    __syncthreads();

    const int w = t >> 5, l = t & 31;
    float a0x = 0.f, a0y = 0.f, a0z = 0.f, a0w = 0.f;
    float a1x = 0.f, a1y = 0.f, a1z = 0.f, a1w = 0.f;
    const float4* __restrict__ W1v = (const float4*)W1;  // [j*32 + l] -> W1[j][4l..4l+3]
    const int j0 = w * 256;
#pragma unroll 4
    for (int j = j0; j < j0 + 256; j++) {
        float4 wv = W1v[j * 32 + l];
        float ca = c0s[j], cb = c1s[j];
        a0x += ca * wv.x; a0y += ca * wv.y; a0z += ca * wv.z; a0w += ca * wv.w;
        a1x += cb * wv.x; a1y += cb * wv.y; a1z += cb * wv.z; a1w += cb * wv.w;
    }
    part[w][0][l * 4 + 0] = a0x; part[w][0][l * 4 + 1] = a0y;
    part[w][0][l * 4 + 2] = a0z; part[w][0][l * 4 + 3] = a0w;
    part[w][1][l * 4 + 0] = a1x; part[w][1][l * 4 + 1] = a1y;
    part[w][1][l * 4 + 2] = a1z; part[w][1][l * 4 + 3] = a1w;
    __syncthreads();

    for (int o = t; o < 2 * HID; o += 128) {
        int bi = o >> 7, h = o & (HID - 1);
        float v = part[0][bi][h] + part[1][bi][h] + part[2][bi][h] + part[3][bi][h] + b1[h];
        g_h1[(b0 + bi) * HID + h] = celu1(v);
    }
}

// ---------------------------------------------------------------------------
// Kernel 3: layers 2+3 — y = celu(h1 @ W2 + b2) @ W3 + b3.
// 128 blocks (one per batch), 128 threads (one per hidden unit).
// ---------------------------------------------------------------------------
__global__ __launch_bounds__(128, 1)
void mlp23_kernel(const float* __restrict__ W2, const float* __restrict__ b2,
                  const float* __restrict__ W3, const float* __restrict__ b3,
                  float* __restrict__ out) {
    __shared__ float h1s[HID];
    __shared__ float rbuf[HID];
    const int b = blockIdx.x, t = threadIdx.x;
    h1s[t] = g_h1[b * HID + t];
    __syncthreads();

    float acc = b2[t];
#pragma unroll 8
    for (int k = 0; k < HID; k++) acc += h1s[k] * W2[k * HID + t];
    acc = celu1(acc);
    rbuf[t] = acc * W3[t];
    __syncthreads();
#pragma unroll
    for (int s = 64; s > 0; s >>= 1) {
        if (t < s) rbuf[t] += rbuf[t + s];
        __syncthreads();
    }
    if (t == 0) out[b] = rbuf[0] + b3[0];
}

// ---------------------------------------------------------------------------
extern "C" void kernel_launch(void* const* d_in, const int* in_sizes, int n_in,
                              void* d_out, int out_size) {
    const float* x  = (const float*)d_in[0];
    const float* W1 = (const float*)d_in[1];
    const float* b1 = (const float*)d_in[2];
    const float* W2 = (const float*)d_in[3];
    const float* b2 = (const float*)d_in[4];
    const float* W3 = (const float*)d_in[5];
    const float* b3 = (const float*)d_in[6];
    float* out = (float*)d_out;

    corr_kernel<<<BATCH, 256>>>(x);
    mlp1_kernel<<<BATCH / 2, 128>>>(W1, b1);
    mlp23_kernel<<<BATCH, 128>>>(W2, b2, W3, b3, out);
}

// round 2
// speedup vs baseline: 1.5019x; 1.5019x over previous
#include <cuda_runtime.h>
#include <cuda_bf16.h>

// ---------------------------------------------------------------------------
// MLP_TI_Gram: y = MLP(mean-of-shifted-diagonal of per-batch Gram matrix)
// diag-mean == circular autocorrelation over sequence dim (3 channels)/N,
// with symmetry c[r] == c[N-r].  B=128, N=1024, H=128.
// ---------------------------------------------------------------------------

#define BATCH 128
#define NSEQ  1024
#define HID   128

__device__ float g_c[BATCH * NSEQ];    // correlation output (scratch)

typedef unsigned long long u64;

// ---- f32x2 packed helpers (Blackwell FFMA2 path, PTX-only) ----------------
__device__ __forceinline__ u64 pk2(float lo, float hi) {
    u64 r;
    asm("mov.b64 %0, {%1,%2};" : "=l"(r) : "f"(lo), "f"(hi));
    return r;
}
__device__ __forceinline__ void upk2(u64 v, float& lo, float& hi) {
    asm("mov.b64 {%0,%1}, %2;" : "=f"(lo), "=f"(hi) : "l"(v));
}
__device__ __forceinline__ u64 fma2(u64 a, u64 b, u64 c) {
    u64 d;
    asm("fma.rn.f32x2 %0, %1, %2, %3;" : "=l"(d) : "l"(a), "l"(b), "l"(c));
    return d;
}

// Bank-conflict padding: logical index i -> physical i + (i>>3).
__device__ __forceinline__ int pbase(int i) { return i + (i >> 3); }

// ---------------------------------------------------------------------------
// Kernel 1: circular autocorrelation with symmetry.
// 128 blocks (one per batch), 512 threads (16 warps -> 4/SMSP).
// Thread t: shift group g = t&63 (8 shifts r0=8g..r0+7),
//           j-split  s = t>>6 (8 splits): m in [64s,64s+64), pairs (m, m+512).
// Channels 0,1 packed per position; channel 2 packed across the two j-halves.
// Sliding register window of width 8; a-loads broadcast within each warp.
// ---------------------------------------------------------------------------
__global__ __launch_bounds__(512, 1)
void corr_kernel(const float* __restrict__ x) {
    // xs01[i] = (x0[i%N], x1[i%N]) for i in [0,1536)
    __shared__ u64 xs01[1736];   // pbase(1535)=1726
    // xs2ab[i] = (x2[i], x2[(i+512)&1023]) for i in [0,1024)
    __shared__ u64 xs2ab[1160];  // pbase(1023)=1150
    __shared__ float red[8][512];

    const int b = blockIdx.x;
    const int t = threadIdx.x;
    const float* __restrict__ xb = x + b * NSEQ * 3;

    for (int i = t; i < 1536; i += 512) {
        int j = i & (NSEQ - 1);
        xs01[pbase(i)] = pk2(xb[j * 3 + 0], xb[j * 3 + 1]);
    }
    for (int i = t; i < 1024; i += 512) {
        xs2ab[pbase(i)] = pk2(xb[i * 3 + 2], xb[((i + 512) & (NSEQ - 1)) * 3 + 2]);
    }
    __syncthreads();

    const int g  = t & 63;
    const int s  = t >> 6;       // 0..7
    const int r0 = g << 3;
    const int mA = s << 6;       // 64-wide m range

    u64 w01a[8], w01b[8], w2[8];
    u64 acc01[8], acc2[8];
#pragma unroll
    for (int k = 0; k < 8; k++) { acc01[k] = 0ull; acc2[k] = 0ull; }

    {
        int bA = pbase(mA + r0);
        int bB = pbase(mA + 512 + r0);
#pragma unroll
        for (int k = 0; k < 8; k++) {
            w01a[k] = xs01[bA + k];
            w01b[k] = xs01[bB + k];
            w2[k]   = xs2ab[bA + k];
        }
    }

#pragma unroll 1
    for (int m = mA; m < mA + 64; m += 8) {
        const int baseA  = pbase(m);
        const int baseB  = pbase(m + 512);
        const int rbaseA = pbase(m + r0 + 8);
        const int rbaseB = pbase(m + 512 + r0 + 8);
#pragma unroll
        for (int u = 0; u < 8; u++) {
            u64 a01a = xs01[baseA + u];
            u64 a01b = xs01[baseB + u];
            u64 a2   = xs2ab[baseA + u];
#pragma unroll
            for (int k = 0; k < 8; k++) {
                int idx = (u + k) & 7;
                acc01[k] = fma2(a01a, w01a[idx], acc01[k]);
                acc01[k] = fma2(a01b, w01b[idx], acc01[k]);
                acc2[k]  = fma2(a2,   w2[idx],   acc2[k]);
            }
            w01a[u] = xs01[rbaseA + u];
            w01b[u] = xs01[rbaseB + u];
            w2[u]   = xs2ab[rbaseA + u];
        }
    }

#pragma unroll
    for (int k = 0; k < 8; k++) {
        float ax, ay, cx, cy;
        upk2(acc01[k], ax, ay);
        upk2(acc2[k],  cx, cy);
        red[s][r0 + k] = ax + ay + cx + cy;
    }
    __syncthreads();

    const float inv = 1.0f / (float)NSEQ;
    {
        int r = t;
        if (r < 512) {
            float v = (red[0][r] + red[1][r] + red[2][r] + red[3][r] +
                       red[4][r] + red[5][r] + red[6][r] + red[7][r]) * inv;
            g_c[b * NSEQ + r] = v;
            if (r > 0) g_c[b * NSEQ + (NSEQ - r)] = v;   // c[r] = c[N-r]
        }
    }

    // r = 512 (self-mirror): c[512] = 2 * sum_{j<512} sum_d xd[j]*xd[j+512]
    if (t < 32) {
        float sum = 0.0f;
        for (int j = t; j < 512; j += 32) {
            float p0x, p0y, q0x, q0y, cx, cy;
            upk2(xs01[pbase(j)], p0x, p0y);
            upk2(xs01[pbase(j + 512)], q0x, q0y);
            upk2(xs2ab[pbase(j)], cx, cy);
            sum += p0x * q0x + p0y * q0y + cx * cy;
        }
        sum *= 2.0f;
#pragma unroll
        for (int o = 16; o > 0; o >>= 1) sum += __shfl_down_sync(0xffffffffu, sum, o);
        if (t == 0) g_c[b * NSEQ + 512] = sum * inv;
    }
}

__device__ __forceinline__ float celu1(float v) {
    return v > 0.0f ? v : expm1f(v);
}

// ---------------------------------------------------------------------------
// Kernel 2: full MLP fused — h1 = celu(c@W1+b1); h2 = celu(h1@W2+b2);
//           y = h2@W3 + b3.
// 64 blocks (one per batch pair), 512 threads = 16 warps.
// Layer 1: warp w covers j in [64w, 64w+64); lane l owns h-quad [4l,4l+4).
//          W1 streamed once per block via LDG.128 (L2-resident after wave 1).
// ---------------------------------------------------------------------------
__global__ __launch_bounds__(512, 1)
void mlp_kernel(const float* __restrict__ W1, const float* __restrict__ b1,
                const float* __restrict__ W2, const float* __restrict__ b2,
                const float* __restrict__ W3, const float* __restrict__ b3,
                float* __restrict__ out) {
    __shared__ u64    csp[NSEQ];            // packed (c0[j], c1[j])  8KB
    __shared__ float4 part4[16][2][32];     // per-warp partials      16KB
    __shared__ float  h1s[2][HID];
    __shared__ float  rbuf[2][HID];

    const int b0 = blockIdx.x * 2;
    const int t  = threadIdx.x;

    for (int i = t; i < NSEQ; i += 512) {
        csp[i] = pk2(g_c[b0 * NSEQ + i], g_c[(b0 + 1) * NSEQ + i]);
    }
    __syncthreads();

    // ---- layer 1 ----
    const int w = t >> 5, l = t & 31;
    float a0x = 0.f, a0y = 0.f, a0z = 0.f, a0w = 0.f;
    float a1x = 0.f, a1y = 0.f, a1z = 0.f, a1w = 0.f;
    const float4* __restrict__ W1v = (const float4*)W1;  // [j*32+l] = W1[j][4l..4l+3]
    const int j0 = w * 64;
#pragma unroll 8
    for (int j = j0; j < j0 + 64; j++) {
        float4 wv = W1v[j * 32 + l];
        float ca, cb;
        upk2(csp[j], ca, cb);
        a0x += ca * wv.x; a0y += ca * wv.y; a0z += ca * wv.z; a0w += ca * wv.w;
        a1x += cb * wv.x; a1y += cb * wv.y; a1z += cb * wv.z; a1w += cb * wv.w;
    }
    part4[w][0][l] = make_float4(a0x, a0y, a0z, a0w);
    part4[w][1][l] = make_float4(a1x, a1y, a1z, a1w);
    __syncthreads();

    if (t < 256) {
        int bi = t >> 7, h = t & (HID - 1);
        const float* p = &((const float*)part4)[0] + (bi * 128 + h);
        float v = b1[h];
#pragma unroll
        for (int ww = 0; ww < 16; ww++) v += p[ww * 256];
        h1s[bi][h] = celu1(v);
    }
    __syncthreads();

    // ---- layers 2 + 3 ----
    if (t < 256) {
        int bi = t >> 7, h = t & (HID - 1);
        float acc = b2[h];
#pragma unroll 8
        for (int k = 0; k < HID; k++) acc += h1s[bi][k] * W2[k * HID + h];
        acc = celu1(acc);
        rbuf[bi][h] = acc * W3[h];
    }
    __syncthreads();
#pragma unroll
    for (int o = 64; o > 0; o >>= 1) {
        if (t < 2 * o) {
            int bi = t >= o ? 1 : 0;
            int h  = t - bi * o;
            rbuf[bi][h] += rbuf[bi][h + o];
        }
        __syncthreads();
    }
    if (t < 2) out[b0 + t] = rbuf[t][0] + b3[0];
}

// ---------------------------------------------------------------------------
extern "C" void kernel_launch(void* const* d_in, const int* in_sizes, int n_in,
                              void* d_out, int out_size) {
    const float* x  = (const float*)d_in[0];
    const float* W1 = (const float*)d_in[1];
    const float* b1 = (const float*)d_in[2];
    const float* W2 = (const float*)d_in[3];
    const float* b2 = (const float*)d_in[4];
    const float* W3 = (const float*)d_in[5];
    const float* b3 = (const float*)d_in[6];
    float* out = (float*)d_out;

    corr_kernel<<<BATCH, 512>>>(x);
    mlp_kernel<<<BATCH / 2, 512>>>(W1, b1, W2, b2, W3, b3, out);
}